// round 14
// baseline (speedup 1.0000x reference)
#include <cuda_runtime.h>
#include <math.h>

// Problem dims (fixed by the dataset)
#define BATCH 1024
#define DMODEL 1568
#define NHEAD 16
#define HSZ 98
#define FFDIM 6272
#define OUTD 784
#define QKVN (3 * DMODEL)   // 4704

// ---------------- scratch (static device globals; no allocs allowed) --------
__device__ float g_h   [BATCH * DMODEL];   // LN1 output
__device__ float g_qkv [BATCH * QKVN];     // fused q|k|v
__device__ float g_attn[BATCH * DMODEL];   // attention output (heads concat)
__device__ float g_proj[BATCH * DMODEL];   // attn @ Wo + bo
__device__ float g_h2  [BATCH * DMODEL];   // LN2 output
__device__ float g_ff1 [BATCH * FFDIM];    // gelu(h2 @ W1 + b1f)
__device__ float g_wqkv[DMODEL * QKVN];    // repacked [D, 3*D] weight

// ---------------- weight repack: Wq/Wk/Wv (H,D,HS) -> [D, 3*D] --------------
__global__ void repack_qkv(const float* __restrict__ Wq,
                           const float* __restrict__ Wk,
                           const float* __restrict__ Wv) {
    const int total = DMODEL * QKVN;
    for (int idx = blockIdx.x * blockDim.x + threadIdx.x; idx < total;
         idx += gridDim.x * blockDim.x) {
        int d     = idx / QKVN;
        int col   = idx - d * QKVN;
        int which = col / DMODEL;
        int c2    = col - which * DMODEL;
        int h     = c2 / HSZ;
        int e     = c2 - h * HSZ;
        const float* W = (which == 0) ? Wq : (which == 1) ? Wk : Wv;
        g_wqkv[idx] = W[(h * DMODEL + d) * HSZ + e];
    }
}

// ---------------- layernorm: one block per row -------------------------------
__global__ void ln_kernel(const float* __restrict__ x,
                          const float* __restrict__ g,
                          const float* __restrict__ b,
                          float* __restrict__ out) {
    const int row = blockIdx.x;
    const float* xr = x + row * DMODEL;
    float s = 0.f, s2 = 0.f;
    for (int i = threadIdx.x; i < DMODEL; i += blockDim.x) {
        float v = xr[i];
        s += v; s2 += v * v;
    }
    __shared__ float red[64];
    for (int o = 16; o; o >>= 1) {
        s  += __shfl_down_sync(0xffffffffu, s,  o);
        s2 += __shfl_down_sync(0xffffffffu, s2, o);
    }
    int wid = threadIdx.x >> 5, lid = threadIdx.x & 31;
    if (lid == 0) { red[wid] = s; red[32 + wid] = s2; }
    __syncthreads();
    if (threadIdx.x == 0) {
        float a = 0.f, a2 = 0.f;
        int nw = blockDim.x >> 5;
        for (int i = 0; i < nw; i++) { a += red[i]; a2 += red[32 + i]; }
        red[0] = a; red[1] = a2;
    }
    __syncthreads();
    float mu  = red[0] * (1.0f / DMODEL);
    float var = red[1] * (1.0f / DMODEL) - mu * mu;
    float inv = rsqrtf(var + 1e-5f);
    float* o = out + row * DMODEL;
    for (int i = threadIdx.x; i < DMODEL; i += blockDim.x)
        o[i] = (xr[i] - mu) * inv * g[i] + b[i];
}

// ---------------- SGEMM 128x128x8, 256 threads, 8x8 micro-tile --------------
// C[M,N] = A[M,K] @ Bm[K,N] (+bias) (+gelu). M % 128 == 0, K % 8 == 0, N % 4 == 0.
template <int ACT>
__global__ __launch_bounds__(256)
void sgemm(const float* __restrict__ A, const float* __restrict__ Bm,
           const float* __restrict__ bias, float* __restrict__ C,
           int M, int N, int K) {
    __shared__ float As[8][128];
    __shared__ float Bs[8][128];
    const int tid = threadIdx.x;
    const int tx = tid & 15;          // 0..15  -> column group
    const int ty = tid >> 4;          // 0..15  -> row group
    const int row0 = blockIdx.y * 128;
    const int col0 = blockIdx.x * 128;

    const int a_row = tid >> 1;           // 0..127
    const int a_col = (tid & 1) * 4;      // 0 or 4
    const int b_row = tid >> 5;           // 0..7
    const int b_col = (tid & 31) * 4;     // 0..124

    float acc[8][8];
#pragma unroll
    for (int i = 0; i < 8; i++)
#pragma unroll
        for (int j = 0; j < 8; j++) acc[i][j] = 0.f;

    const float* Aptr = A + (size_t)(row0 + a_row) * K + a_col;
    const int gcol = col0 + b_col;
    const bool bok = (gcol < N);

    for (int k0 = 0; k0 < K; k0 += 8) {
        float4 av = *(const float4*)(Aptr + k0);
        As[a_col + 0][a_row] = av.x;
        As[a_col + 1][a_row] = av.y;
        As[a_col + 2][a_row] = av.z;
        As[a_col + 3][a_row] = av.w;
        float4 bv = make_float4(0.f, 0.f, 0.f, 0.f);
        if (bok) bv = *(const float4*)(Bm + (size_t)(k0 + b_row) * N + gcol);
        *(float4*)&Bs[b_row][b_col] = bv;
        __syncthreads();
#pragma unroll
        for (int k = 0; k < 8; k++) {
            float af[8], bf[8];
            *(float4*)(af)     = *(const float4*)&As[k][ty * 8];
            *(float4*)(af + 4) = *(const float4*)&As[k][ty * 8 + 4];
            *(float4*)(bf)     = *(const float4*)&Bs[k][tx * 8];
            *(float4*)(bf + 4) = *(const float4*)&Bs[k][tx * 8 + 4];
#pragma unroll
            for (int i = 0; i < 8; i++)
#pragma unroll
                for (int j = 0; j < 8; j++)
                    acc[i][j] = fmaf(af[i], bf[j], acc[i][j]);
        }
        __syncthreads();
    }

#pragma unroll
    for (int i = 0; i < 8; i++) {
        int r = row0 + ty * 8 + i;
#pragma unroll
        for (int j = 0; j < 8; j++) {
            int c = col0 + tx * 8 + j;
            if (c < N) {
                float v = acc[i][j];
                if (bias) v += bias[c];
                if (ACT == 1) v = 0.5f * v * (1.0f + erff(v * 0.70710678118654752f));
                C[(size_t)r * N + c] = v;
            }
        }
    }
}

// ---------------- rank-1 pseudo-attention -----------------------------------
// per (b,h): logits_ij = (q_i * s) * k_j ; softmax over j ; out_i = sum p_ij v_j
__global__ __launch_bounds__(128)
void attn_kernel(const float* __restrict__ qkv, float* __restrict__ out) {
    const int bh = blockIdx.x;
    const int b = bh >> 4;        // / NHEAD
    const int h = bh & 15;        // % NHEAD
    const float* q = qkv + (size_t)b * QKVN + h * HSZ;
    const float* k = q + DMODEL;
    const float* v = q + 2 * DMODEL;

    __shared__ float ks[HSZ], vs[HSZ], qs[HSZ];
    __shared__ float kext[2];
    const int tid = threadIdx.x;
    if (tid < HSZ) { ks[tid] = k[tid]; vs[tid] = v[tid]; qs[tid] = q[tid]; }
    __syncthreads();
    if (tid < 32) {
        float mx = -1e30f, mn = 1e30f;
        for (int j = tid; j < HSZ; j += 32) {
            mx = fmaxf(mx, ks[j]);
            mn = fminf(mn, ks[j]);
        }
        for (int o = 16; o; o >>= 1) {
            mx = fmaxf(mx, __shfl_xor_sync(0xffffffffu, mx, o));
            mn = fminf(mn, __shfl_xor_sync(0xffffffffu, mn, o));
        }
        if (tid == 0) { kext[0] = mx; kext[1] = mn; }
    }
    __syncthreads();
    if (tid < HSZ) {
        const float scale = 0.025253813613805268f;  // 1568^-0.5
        float a = qs[tid] * scale;
        float m = a * ((a >= 0.f) ? kext[0] : kext[1]);
        float sum = 0.f, acc = 0.f;
#pragma unroll 7
        for (int j = 0; j < HSZ; j++) {
            float e = __expf(fmaf(a, ks[j], -m));
            sum += e;
            acc = fmaf(e, vs[j], acc);
        }
        out[(size_t)b * DMODEL + h * HSZ + tid] = acc / sum;
    }
}

// ---------------- launch ------------------------------------------------------
extern "C" void kernel_launch(void* const* d_in, const int* in_sizes, int n_in,
                              void* d_out, int out_size) {
    const float* x   = (const float*)d_in[0];
    const float* Wq  = (const float*)d_in[1];
    const float* Wk  = (const float*)d_in[2];
    const float* Wv  = (const float*)d_in[3];
    const float* Wo  = (const float*)d_in[4];
    const float* bo  = (const float*)d_in[5];
    const float* g1  = (const float*)d_in[6];
    const float* b1  = (const float*)d_in[7];
    const float* g2  = (const float*)d_in[8];
    const float* b2  = (const float*)d_in[9];
    const float* W1  = (const float*)d_in[10];
    const float* b1f = (const float*)d_in[11];
    const float* W2  = (const float*)d_in[12];
    const float* b2f = (const float*)d_in[13];
    float* outp = (float*)d_out;

    // symbol addresses (host-side lookups; capture-safe, no stream ops)
    float *p_h, *p_qkv, *p_attn, *p_proj, *p_h2, *p_ff1, *p_wqkv;
    cudaGetSymbolAddress((void**)&p_h,    g_h);
    cudaGetSymbolAddress((void**)&p_qkv,  g_qkv);
    cudaGetSymbolAddress((void**)&p_attn, g_attn);
    cudaGetSymbolAddress((void**)&p_proj, g_proj);
    cudaGetSymbolAddress((void**)&p_h2,   g_h2);
    cudaGetSymbolAddress((void**)&p_ff1,  g_ff1);
    cudaGetSymbolAddress((void**)&p_wqkv, g_wqkv);

    // 0) repack qkv weights -> [D, 3D]
    repack_qkv<<<512, 256>>>(Wq, Wk, Wv);

    // 1) LN1
    ln_kernel<<<BATCH, 256>>>(x, g1, b1, p_h);

    // 2) qkv = h @ Wqkv   (1024 x 4704)
    {
        dim3 grid((QKVN + 127) / 128, BATCH / 128);
        sgemm<0><<<grid, 256>>>(p_h, p_wqkv, nullptr, p_qkv, BATCH, QKVN, DMODEL);
    }

    // 3) attention
    attn_kernel<<<BATCH * NHEAD, 128>>>(p_qkv, p_attn);

    // 4) proj = attn @ Wo + bo
    {
        dim3 grid((DMODEL + 127) / 128, BATCH / 128);
        sgemm<0><<<grid, 256>>>(p_attn, Wo, bo, p_proj, BATCH, DMODEL, DMODEL);
    }

    // 5) LN2
    ln_kernel<<<BATCH, 256>>>(p_proj, g2, b2, p_h2);

    // 6) ff1 = gelu(h2 @ W1 + b1f)
    {
        dim3 grid((FFDIM + 127) / 128, BATCH / 128);
        sgemm<1><<<grid, 256>>>(p_h2, W1, b1f, p_ff1, BATCH, FFDIM, DMODEL);
    }

    // 7) out = ff1 @ W2 + b2f
    {
        dim3 grid((OUTD + 127) / 128, BATCH / 128);
        sgemm<0><<<grid, 256>>>(p_ff1, W2, b2f, outp, BATCH, OUTD, FFDIM);
    }
}

// round 16
// speedup vs baseline: 3.0879x; 3.0879x over previous
#include <cuda_runtime.h>
#include <cuda_bf16.h>
#include <cstdint>
#include <math.h>

// ---------------- problem dims ------------------------------------------------
#define BATCH 1024
#define DMODEL 1568
#define NHEAD 16
#define HSZ 98
#define FFDIM 6272
#define OUTD 784
#define QKVN (3 * DMODEL)   // 4704

// padded dims
#define KP_D 1600           // DMODEL -> mult of 32
#define KP_F 6272           // FFDIM already mult of 32
#define NP_QKV 4736         // 37 * 128
#define NP_WO  1664         // 13 * 128
#define NP_W1  6272         // 49 * 128
#define NP_W2  896          //  7 * 128

// ---------------- scratch (static device globals) -----------------------------
__device__ float g_h   [BATCH * DMODEL];
__device__ float g_qkv [BATCH * QKVN];
__device__ float g_attn[BATCH * DMODEL];
__device__ float g_proj[BATCH * DMODEL];
__device__ float g_h2  [BATCH * DMODEL];
__device__ float g_ff1 [BATCH * FFDIM];
__device__ float g_wqkv[DMODEL * QKVN];

// bf16 hi/lo operand buffers (row-major, K contiguous)
__device__ __nv_bfloat16 g_Ah [BATCH * KP_F];
__device__ __nv_bfloat16 g_Al [BATCH * KP_F];
__device__ __nv_bfloat16 g_qBh[NP_QKV * KP_D];
__device__ __nv_bfloat16 g_qBl[NP_QKV * KP_D];
__device__ __nv_bfloat16 g_oBh[NP_WO * KP_D];
__device__ __nv_bfloat16 g_oBl[NP_WO * KP_D];
__device__ __nv_bfloat16 g_1Bh[NP_W1 * KP_D];
__device__ __nv_bfloat16 g_1Bl[NP_W1 * KP_D];
__device__ __nv_bfloat16 g_2Bh[NP_W2 * KP_F];
__device__ __nv_bfloat16 g_2Bl[NP_W2 * KP_F];

// ---------------- PTX helpers ---------------------------------------------------
__device__ __forceinline__ uint32_t smem_u32(const void* p) {
    uint32_t a;
    asm("{ .reg .u64 t; cvta.to.shared.u64 t, %1; cvt.u32.u64 %0, t; }" : "=r"(a) : "l"(p));
    return a;
}
__device__ __forceinline__ void cp16(uint32_t dst, const void* src) {
    asm volatile("cp.async.cg.shared.global [%0], [%1], 16;" :: "r"(dst), "l"(src));
}
__device__ __forceinline__ void cp_commit() {
    asm volatile("cp.async.commit_group;");
}
template <int N>
__device__ __forceinline__ void cp_wait() {
    asm volatile("cp.async.wait_group %0;" :: "n"(N));
}
__device__ __forceinline__ void ldm4(uint32_t* r, uint32_t addr) {
    asm volatile("ldmatrix.sync.aligned.m8n8.x4.shared.b16 {%0,%1,%2,%3}, [%4];"
                 : "=r"(r[0]), "=r"(r[1]), "=r"(r[2]), "=r"(r[3]) : "r"(addr));
}
__device__ __forceinline__ void mma_bf16(float* c, const uint32_t* a, const uint32_t* b) {
    asm volatile(
        "mma.sync.aligned.m16n8k16.row.col.f32.bf16.bf16.f32 "
        "{%0,%1,%2,%3}, {%4,%5,%6,%7}, {%8,%9}, {%0,%1,%2,%3};"
        : "+f"(c[0]), "+f"(c[1]), "+f"(c[2]), "+f"(c[3])
        : "r"(a[0]), "r"(a[1]), "r"(a[2]), "r"(a[3]), "r"(b[0]), "r"(b[1]));
}

// ---------------- weight repack: Wq/Wk/Wv (H,D,HS) -> [D, 3*D] fp32 -------------
__global__ void repack_qkv(const float* __restrict__ Wq,
                           const float* __restrict__ Wk,
                           const float* __restrict__ Wv) {
    const int total = DMODEL * QKVN;
    for (int idx = blockIdx.x * blockDim.x + threadIdx.x; idx < total;
         idx += gridDim.x * blockDim.x) {
        int d     = idx / QKVN;
        int col   = idx - d * QKVN;
        int which = col / DMODEL;
        int c2    = col - which * DMODEL;
        int h     = c2 / HSZ;
        int e     = c2 - h * HSZ;
        const float* W = (which == 0) ? Wq : (which == 1) ? Wk : Wv;
        g_wqkv[idx] = W[(h * DMODEL + d) * HSZ + e];
    }
}

// ---------------- transpose repack: W[K,N] fp32 -> Bt[Npad,Kpad] bf16 hi/lo -----
__global__ __launch_bounds__(256)
void repack_Bt(const float* __restrict__ W, int K, int N, int Kpad,
               __nv_bfloat16* __restrict__ Bh, __nv_bfloat16* __restrict__ Bl) {
    __shared__ float t[32][33];
    const int k0 = blockIdx.x * 32, n0 = blockIdx.y * 32;
    const int tx = threadIdx.x & 31, ty = threadIdx.x >> 5;  // 32 x 8
#pragma unroll
    for (int i = ty; i < 32; i += 8) {
        int k = k0 + i, n = n0 + tx;
        t[i][tx] = (k < K && n < N) ? W[(size_t)k * N + n] : 0.f;
    }
    __syncthreads();
#pragma unroll
    for (int i = ty; i < 32; i += 8) {
        int n = n0 + i, k = k0 + tx;
        float v = t[tx][i];
        __nv_bfloat16 h = __float2bfloat16(v);
        __nv_bfloat16 l = __float2bfloat16(v - __bfloat162float(h));
        size_t o = (size_t)n * Kpad + k;
        Bh[o] = h; Bl[o] = l;
    }
}

// ---------------- A repack: A[1024,K] fp32 -> [1024,Kpad] bf16 hi/lo -------------
__global__ __launch_bounds__(256)
void repack_Ab(const float* __restrict__ A, int K, int Kpad,
               __nv_bfloat16* __restrict__ Ah, __nv_bfloat16* __restrict__ Al) {
    int k = blockIdx.x * 256 + threadIdx.x;
    int r = blockIdx.y;
    if (k < Kpad) {
        float v = (k < K) ? A[(size_t)r * K + k] : 0.f;
        __nv_bfloat16 h = __float2bfloat16(v);
        __nv_bfloat16 l = __float2bfloat16(v - __bfloat162float(h));
        size_t o = (size_t)r * Kpad + k;
        Ah[o] = h; Al[o] = l;
    }
}

// ---------------- bf16 3-pass MMA GEMM: C[1024,N] = A @ B^T (+bias)(+gelu) ------
// tile 128x128x32, 8 warps (2m x 4n), each warp 64x32 via m16n8k16 atoms.
// smem stage: Ah(10240) Al(10240) Bh(10240) Bl(10240) = 40960B; 2 stages = 81920B.
// row pitch 80B (64B data + 16B pad) -> conflict-free ldmatrix.
#define SA_L 10240u
#define SB_H 20480u
#define SB_L 30720u
#define STG  40960u

__device__ __forceinline__ void load_stage(uint32_t sbase,
    const __nv_bfloat16* Ah, const __nv_bfloat16* Al,
    const __nv_bfloat16* Bh, const __nv_bfloat16* Bl,
    int arow0, int brow0, int Kpad, int k0, int tid)
{
#pragma unroll
    for (int hh = 0; hh < 2; hh++) {
        int c = tid + hh * 256;
        int r = c >> 2, j = c & 3;
        size_t goA = (size_t)(arow0 + r) * Kpad + k0 + j * 8;
        size_t goB = (size_t)(brow0 + r) * Kpad + k0 + j * 8;
        uint32_t so = (uint32_t)(r * 80 + j * 16);
        cp16(sbase + so,        Ah + goA);
        cp16(sbase + SA_L + so, Al + goA);
        cp16(sbase + SB_H + so, Bh + goB);
        cp16(sbase + SB_L + so, Bl + goB);
    }
}

__global__ __launch_bounds__(256)
void gemm_mma(const __nv_bfloat16* __restrict__ Ah, const __nv_bfloat16* __restrict__ Al,
              const __nv_bfloat16* __restrict__ Bh, const __nv_bfloat16* __restrict__ Bl,
              const float* __restrict__ bias, float* __restrict__ C,
              int N, int Kpad, int act) {
    extern __shared__ char smem[];
    const uint32_t s0 = smem_u32(smem);
    const int tid = threadIdx.x, lane = tid & 31, wid = tid >> 5;
    const int wm = wid >> 2, wn = wid & 3;          // 2 x 4 warp grid
    const int nt = blockIdx.x, mt = blockIdx.y;
    const int arow0 = mt * 128, brow0 = nt * 128;
    const int nIter = Kpad / 32;

    float acc[4][4][4];
#pragma unroll
    for (int i = 0; i < 4; i++)
#pragma unroll
        for (int j = 0; j < 4; j++)
#pragma unroll
            for (int r = 0; r < 4; r++) acc[i][j][r] = 0.f;

    load_stage(s0, Ah, Al, Bh, Bl, arow0, brow0, Kpad, 0, tid);
    cp_commit();

    const int lr = lane & 15, lc = lane >> 4;                       // A ldmatrix addr
    const int br = (lane & 7) + ((lane >> 4) & 1) * 8;              // B ldmatrix addr
    const int bc = (lane >> 3) & 1;

    for (int it = 0; it < nIter; it++) {
        if (it + 1 < nIter) {
            load_stage(s0 + ((it + 1) & 1) * STG, Ah, Al, Bh, Bl,
                       arow0, brow0, Kpad, (it + 1) * 32, tid);
            cp_commit();
            cp_wait<1>();
        } else {
            cp_wait<0>();
        }
        __syncthreads();
        const uint32_t base = s0 + (it & 1) * STG;
#pragma unroll
        for (int ks = 0; ks < 2; ks++) {
            uint32_t ah[4][4], al[4][4], bh[4][2], bl[4][2];
#pragma unroll
            for (int ma = 0; ma < 4; ma++) {
                uint32_t addr = base + (uint32_t)((wm * 64 + ma * 16 + lr) * 80 + ks * 32 + lc * 16);
                ldm4(ah[ma], addr);
                ldm4(al[ma], addr + SA_L);
            }
#pragma unroll
            for (int nb = 0; nb < 2; nb++) {
                uint32_t addr = base + SB_H + (uint32_t)((wn * 32 + nb * 16 + br) * 80 + ks * 32 + bc * 16);
                uint32_t tmp[4];
                ldm4(tmp, addr);
                bh[nb * 2][0] = tmp[0]; bh[nb * 2][1] = tmp[1];
                bh[nb * 2 + 1][0] = tmp[2]; bh[nb * 2 + 1][1] = tmp[3];
                ldm4(tmp, addr + SA_L);
                bl[nb * 2][0] = tmp[0]; bl[nb * 2][1] = tmp[1];
                bl[nb * 2 + 1][0] = tmp[2]; bl[nb * 2 + 1][1] = tmp[3];
            }
#pragma unroll
            for (int ma = 0; ma < 4; ma++)
#pragma unroll
                for (int na = 0; na < 4; na++) mma_bf16(acc[ma][na], ah[ma], bh[na]);
#pragma unroll
            for (int ma = 0; ma < 4; ma++)
#pragma unroll
                for (int na = 0; na < 4; na++) mma_bf16(acc[ma][na], ah[ma], bl[na]);
#pragma unroll
            for (int ma = 0; ma < 4; ma++)
#pragma unroll
                for (int na = 0; na < 4; na++) mma_bf16(acc[ma][na], al[ma], bh[na]);
        }
        __syncthreads();
    }

    // epilogue: d0,d1 -> (row, col..col+1); d2,d3 -> (row+8, ...)
    const int rbase = mt * 128 + wm * 64 + (lane >> 2);
    const int cbase = nt * 128 + wn * 32 + (lane & 3) * 2;
#pragma unroll
    for (int ma = 0; ma < 4; ma++) {
#pragma unroll
        for (int na = 0; na < 4; na++) {
            int col = cbase + na * 8;
            if (col < N) {
                float b0 = 0.f, b1 = 0.f;
                if (bias) { b0 = bias[col]; b1 = bias[col + 1]; }
#pragma unroll
                for (int half = 0; half < 2; half++) {
                    int row = rbase + ma * 16 + half * 8;
                    float v0 = acc[ma][na][half * 2 + 0] + b0;
                    float v1 = acc[ma][na][half * 2 + 1] + b1;
                    if (act) {
                        v0 = 0.5f * v0 * (1.0f + erff(v0 * 0.70710678118654752f));
                        v1 = 0.5f * v1 * (1.0f + erff(v1 * 0.70710678118654752f));
                    }
                    *(float2*)(C + (size_t)row * N + col) = make_float2(v0, v1);
                }
            }
        }
    }
}

// ---------------- layernorm ----------------------------------------------------
__global__ void ln_kernel(const float* __restrict__ x,
                          const float* __restrict__ g,
                          const float* __restrict__ b,
                          float* __restrict__ out) {
    const int row = blockIdx.x;
    const float* xr = x + row * DMODEL;
    float s = 0.f, s2 = 0.f;
    for (int i = threadIdx.x; i < DMODEL; i += blockDim.x) {
        float v = xr[i];
        s += v; s2 += v * v;
    }
    __shared__ float red[64];
    for (int o = 16; o; o >>= 1) {
        s  += __shfl_down_sync(0xffffffffu, s,  o);
        s2 += __shfl_down_sync(0xffffffffu, s2, o);
    }
    int wid = threadIdx.x >> 5, lid = threadIdx.x & 31;
    if (lid == 0) { red[wid] = s; red[32 + wid] = s2; }
    __syncthreads();
    if (threadIdx.x == 0) {
        float a = 0.f, a2 = 0.f;
        int nw = blockDim.x >> 5;
        for (int i = 0; i < nw; i++) { a += red[i]; a2 += red[32 + i]; }
        red[0] = a; red[1] = a2;
    }
    __syncthreads();
    float mu  = red[0] * (1.0f / DMODEL);
    float var = red[1] * (1.0f / DMODEL) - mu * mu;
    float inv = rsqrtf(var + 1e-5f);
    float* o = out + row * DMODEL;
    for (int i = threadIdx.x; i < DMODEL; i += blockDim.x)
        o[i] = (xr[i] - mu) * inv * g[i] + b[i];
}

// ---------------- rank-1 pseudo-attention ---------------------------------------
__global__ __launch_bounds__(128)
void attn_kernel(const float* __restrict__ qkv, float* __restrict__ out) {
    const int bh = blockIdx.x;
    const int b = bh >> 4;
    const int h = bh & 15;
    const float* q = qkv + (size_t)b * QKVN + h * HSZ;
    const float* k = q + DMODEL;
    const float* v = q + 2 * DMODEL;

    __shared__ float ks[HSZ], vs[HSZ], qs[HSZ];
    __shared__ float kext[2];
    const int tid = threadIdx.x;
    if (tid < HSZ) { ks[tid] = k[tid]; vs[tid] = v[tid]; qs[tid] = q[tid]; }
    __syncthreads();
    if (tid < 32) {
        float mx = -1e30f, mn = 1e30f;
        for (int j = tid; j < HSZ; j += 32) {
            mx = fmaxf(mx, ks[j]);
            mn = fminf(mn, ks[j]);
        }
        for (int o = 16; o; o >>= 1) {
            mx = fmaxf(mx, __shfl_xor_sync(0xffffffffu, mx, o));
            mn = fminf(mn, __shfl_xor_sync(0xffffffffu, mn, o));
        }
        if (tid == 0) { kext[0] = mx; kext[1] = mn; }
    }
    __syncthreads();
    if (tid < HSZ) {
        const float scale = 0.025253813613805268f;  // 1568^-0.5
        float a = qs[tid] * scale;
        float m = a * ((a >= 0.f) ? kext[0] : kext[1]);
        float sum = 0.f, acc = 0.f;
#pragma unroll 7
        for (int j = 0; j < HSZ; j++) {
            float e = __expf(fmaf(a, ks[j], -m));
            sum += e;
            acc = fmaf(e, vs[j], acc);
        }
        out[(size_t)b * DMODEL + h * HSZ + tid] = acc / sum;
    }
}

// ---------------- launch ---------------------------------------------------------
extern "C" void kernel_launch(void* const* d_in, const int* in_sizes, int n_in,
                              void* d_out, int out_size) {
    const float* x   = (const float*)d_in[0];
    const float* Wq  = (const float*)d_in[1];
    const float* Wk  = (const float*)d_in[2];
    const float* Wv  = (const float*)d_in[3];
    const float* Wo  = (const float*)d_in[4];
    const float* bo  = (const float*)d_in[5];
    const float* g1  = (const float*)d_in[6];
    const float* b1  = (const float*)d_in[7];
    const float* g2  = (const float*)d_in[8];
    const float* b2  = (const float*)d_in[9];
    const float* W1  = (const float*)d_in[10];
    const float* b1f = (const float*)d_in[11];
    const float* W2  = (const float*)d_in[12];
    const float* b2f = (const float*)d_in[13];
    float* outp = (float*)d_out;

    float *p_h, *p_qkv, *p_attn, *p_proj, *p_h2, *p_ff1, *p_wqkv;
    __nv_bfloat16 *pAh, *pAl, *pqBh, *pqBl, *poBh, *poBl, *p1Bh, *p1Bl, *p2Bh, *p2Bl;
    cudaGetSymbolAddress((void**)&p_h,    g_h);
    cudaGetSymbolAddress((void**)&p_qkv,  g_qkv);
    cudaGetSymbolAddress((void**)&p_attn, g_attn);
    cudaGetSymbolAddress((void**)&p_proj, g_proj);
    cudaGetSymbolAddress((void**)&p_h2,   g_h2);
    cudaGetSymbolAddress((void**)&p_ff1,  g_ff1);
    cudaGetSymbolAddress((void**)&p_wqkv, g_wqkv);
    cudaGetSymbolAddress((void**)&pAh,  g_Ah);
    cudaGetSymbolAddress((void**)&pAl,  g_Al);
    cudaGetSymbolAddress((void**)&pqBh, g_qBh);
    cudaGetSymbolAddress((void**)&pqBl, g_qBl);
    cudaGetSymbolAddress((void**)&poBh, g_oBh);
    cudaGetSymbolAddress((void**)&poBl, g_oBl);
    cudaGetSymbolAddress((void**)&p1Bh, g_1Bh);
    cudaGetSymbolAddress((void**)&p1Bl, g_1Bl);
    cudaGetSymbolAddress((void**)&p2Bh, g_2Bh);
    cudaGetSymbolAddress((void**)&p2Bl, g_2Bl);

    const int SMEM_GEMM = 81920;
    cudaFuncSetAttribute(gemm_mma, cudaFuncAttributeMaxDynamicSharedMemorySize, SMEM_GEMM);

    // 0) weight repacks -> transposed bf16 hi/lo [Npad, Kpad]
    repack_qkv<<<512, 256>>>(Wq, Wk, Wv);
    repack_Bt<<<dim3(KP_D / 32, NP_QKV / 32), 256>>>(p_wqkv, DMODEL, QKVN, KP_D, pqBh, pqBl);
    repack_Bt<<<dim3(KP_D / 32, NP_WO  / 32), 256>>>(Wo,     DMODEL, DMODEL, KP_D, poBh, poBl);
    repack_Bt<<<dim3(KP_D / 32, NP_W1  / 32), 256>>>(W1,     DMODEL, FFDIM,  KP_D, p1Bh, p1Bl);
    repack_Bt<<<dim3(KP_F / 32, NP_W2  / 32), 256>>>(W2,     FFDIM,  OUTD,   KP_F, p2Bh, p2Bl);

    // 1) LN1
    ln_kernel<<<BATCH, 256>>>(x, g1, b1, p_h);

    // 2) qkv = h @ Wqkv
    repack_Ab<<<dim3((KP_D + 255) / 256, BATCH), 256>>>(p_h, DMODEL, KP_D, pAh, pAl);
    gemm_mma<<<dim3(NP_QKV / 128, 8), 256, SMEM_GEMM>>>(pAh, pAl, pqBh, pqBl, nullptr, p_qkv, QKVN, KP_D, 0);

    // 3) attention
    attn_kernel<<<BATCH * NHEAD, 128>>>(p_qkv, p_attn);

    // 4) proj = attn @ Wo + bo
    repack_Ab<<<dim3((KP_D + 255) / 256, BATCH), 256>>>(p_attn, DMODEL, KP_D, pAh, pAl);
    gemm_mma<<<dim3(NP_WO / 128, 8), 256, SMEM_GEMM>>>(pAh, pAl, poBh, poBl, bo, p_proj, DMODEL, KP_D, 0);

    // 5) LN2
    ln_kernel<<<BATCH, 256>>>(p_proj, g2, b2, p_h2);

    // 6) ff1 = gelu(h2 @ W1 + b1f)
    repack_Ab<<<dim3((KP_D + 255) / 256, BATCH), 256>>>(p_h2, DMODEL, KP_D, pAh, pAl);
    gemm_mma<<<dim3(NP_W1 / 128, 8), 256, SMEM_GEMM>>>(pAh, pAl, p1Bh, p1Bl, b1f, p_ff1, FFDIM, KP_D, 1);

    // 7) out = ff1 @ W2 + b2f
    repack_Ab<<<dim3((KP_F + 255) / 256, BATCH), 256>>>(p_ff1, FFDIM, KP_F, pAh, pAl);
    gemm_mma<<<dim3(NP_W2 / 128, 8), 256, SMEM_GEMM>>>(pAh, pAl, p2Bh, p2Bl, b2f, outp, OUTD, KP_F, 0);
}

// round 17
// speedup vs baseline: 3.0961x; 1.0027x over previous
#include <cuda_runtime.h>
#include <cuda_bf16.h>
#include <cstdint>
#include <math.h>

// ---------------- problem dims ------------------------------------------------
#define BATCH 1024
#define DMODEL 1568
#define NHEAD 16
#define HSZ 98
#define FFDIM 6272
#define OUTD 784
#define QKVN (3 * DMODEL)   // 4704

// padded dims
#define KP_D 1600           // DMODEL -> mult of 32
#define KP_F 6272           // FFDIM already mult of 32
#define NP_QKV 4736         // 37 * 128
#define NP_WO  1664         // 13 * 128
#define NP_W1  6272         // 49 * 128
#define NP_W2  896          //  7 * 128

// ---------------- scratch (static device globals) -----------------------------
__device__ float g_h   [BATCH * DMODEL];
__device__ float g_qkv [BATCH * QKVN];
__device__ float g_attn[BATCH * DMODEL];
__device__ float g_proj[BATCH * DMODEL];
__device__ float g_h2  [BATCH * DMODEL];
__device__ float g_ff1 [BATCH * FFDIM];
__device__ float g_wqkv[DMODEL * QKVN];

// bf16 hi/lo operand buffers (row-major, K contiguous)
__device__ __nv_bfloat16 g_Ah [BATCH * KP_F];
__device__ __nv_bfloat16 g_Al [BATCH * KP_F];
__device__ __nv_bfloat16 g_qBh[NP_QKV * KP_D];
__device__ __nv_bfloat16 g_qBl[NP_QKV * KP_D];
__device__ __nv_bfloat16 g_oBh[NP_WO * KP_D];
__device__ __nv_bfloat16 g_oBl[NP_WO * KP_D];
__device__ __nv_bfloat16 g_1Bh[NP_W1 * KP_D];
__device__ __nv_bfloat16 g_1Bl[NP_W1 * KP_D];
__device__ __nv_bfloat16 g_2Bh[NP_W2 * KP_F];
__device__ __nv_bfloat16 g_2Bl[NP_W2 * KP_F];

// ---------------- PTX helpers ---------------------------------------------------
__device__ __forceinline__ uint32_t smem_u32(const void* p) {
    uint32_t a;
    asm("{ .reg .u64 t; cvta.to.shared.u64 t, %1; cvt.u32.u64 %0, t; }" : "=r"(a) : "l"(p));
    return a;
}
__device__ __forceinline__ void cp16(uint32_t dst, const void* src) {
    asm volatile("cp.async.cg.shared.global [%0], [%1], 16;" :: "r"(dst), "l"(src));
}
__device__ __forceinline__ void cp_commit() {
    asm volatile("cp.async.commit_group;");
}
template <int N>
__device__ __forceinline__ void cp_wait() {
    asm volatile("cp.async.wait_group %0;" :: "n"(N));
}
__device__ __forceinline__ void ldm4(uint32_t* r, uint32_t addr) {
    asm volatile("ldmatrix.sync.aligned.m8n8.x4.shared.b16 {%0,%1,%2,%3}, [%4];"
                 : "=r"(r[0]), "=r"(r[1]), "=r"(r[2]), "=r"(r[3]) : "r"(addr));
}
__device__ __forceinline__ void mma_bf16(float* c, const uint32_t* a, const uint32_t* b) {
    asm volatile(
        "mma.sync.aligned.m16n8k16.row.col.f32.bf16.bf16.f32 "
        "{%0,%1,%2,%3}, {%4,%5,%6,%7}, {%8,%9}, {%0,%1,%2,%3};"
        : "+f"(c[0]), "+f"(c[1]), "+f"(c[2]), "+f"(c[3])
        : "r"(a[0]), "r"(a[1]), "r"(a[2]), "r"(a[3]), "r"(b[0]), "r"(b[1]));
}

// ---------------- weight repack: Wq/Wk/Wv (H,D,HS) -> [D, 3*D] fp32 -------------
__global__ void repack_qkv(const float* __restrict__ Wq,
                           const float* __restrict__ Wk,
                           const float* __restrict__ Wv) {
    const int total = DMODEL * QKVN;
    for (int idx = blockIdx.x * blockDim.x + threadIdx.x; idx < total;
         idx += gridDim.x * blockDim.x) {
        int d     = idx / QKVN;
        int col   = idx - d * QKVN;
        int which = col / DMODEL;
        int c2    = col - which * DMODEL;
        int h     = c2 / HSZ;
        int e     = c2 - h * HSZ;
        const float* W = (which == 0) ? Wq : (which == 1) ? Wk : Wv;
        g_wqkv[idx] = W[(h * DMODEL + d) * HSZ + e];
    }
}

// ---------------- transpose repack: W[K,N] fp32 -> Bt[Npad,Kpad] bf16 hi/lo -----
__global__ __launch_bounds__(256)
void repack_Bt(const float* __restrict__ W, int K, int N, int Kpad,
               __nv_bfloat16* __restrict__ Bh, __nv_bfloat16* __restrict__ Bl) {
    __shared__ float t[32][33];
    const int k0 = blockIdx.x * 32, n0 = blockIdx.y * 32;
    const int tx = threadIdx.x & 31, ty = threadIdx.x >> 5;  // 32 x 8
#pragma unroll
    for (int i = ty; i < 32; i += 8) {
        int k = k0 + i, n = n0 + tx;
        t[i][tx] = (k < K && n < N) ? W[(size_t)k * N + n] : 0.f;
    }
    __syncthreads();
#pragma unroll
    for (int i = ty; i < 32; i += 8) {
        int n = n0 + i, k = k0 + tx;
        float v = t[tx][i];
        __nv_bfloat16 h = __float2bfloat16(v);
        __nv_bfloat16 l = __float2bfloat16(v - __bfloat162float(h));
        size_t o = (size_t)n * Kpad + k;
        Bh[o] = h; Bl[o] = l;
    }
}

// ---------------- A repack: A[1024,K] fp32 -> [1024,Kpad] bf16 hi/lo -------------
__global__ __launch_bounds__(256)
void repack_Ab(const float* __restrict__ A, int K, int Kpad,
               __nv_bfloat16* __restrict__ Ah, __nv_bfloat16* __restrict__ Al) {
    int k = blockIdx.x * 256 + threadIdx.x;
    int r = blockIdx.y;
    if (k < Kpad) {
        float v = (k < K) ? A[(size_t)r * K + k] : 0.f;
        __nv_bfloat16 h = __float2bfloat16(v);
        __nv_bfloat16 l = __float2bfloat16(v - __bfloat162float(h));
        size_t o = (size_t)r * Kpad + k;
        Ah[o] = h; Al[o] = l;
    }
}

// ---------------- bf16 3-pass MMA GEMM: C[1024,N] = A @ B^T (+bias)(+gelu) ------
// tile 128x128x32, 8 warps (2m x 4n), each warp 64x32 via m16n8k16 atoms.
// smem stage: Ah(10240) Al(10240) Bh(10240) Bl(10240) = 40960B; 2 stages = 81920B.
// row pitch 80B (64B data + 16B pad) -> conflict-free ldmatrix.
#define SA_L 10240u
#define SB_H 20480u
#define SB_L 30720u
#define STG  40960u

__device__ __forceinline__ void load_stage(uint32_t sbase,
    const __nv_bfloat16* Ah, const __nv_bfloat16* Al,
    const __nv_bfloat16* Bh, const __nv_bfloat16* Bl,
    int arow0, int brow0, int Kpad, int k0, int tid)
{
#pragma unroll
    for (int hh = 0; hh < 2; hh++) {
        int c = tid + hh * 256;
        int r = c >> 2, j = c & 3;
        size_t goA = (size_t)(arow0 + r) * Kpad + k0 + j * 8;
        size_t goB = (size_t)(brow0 + r) * Kpad + k0 + j * 8;
        uint32_t so = (uint32_t)(r * 80 + j * 16);
        cp16(sbase + so,        Ah + goA);
        cp16(sbase + SA_L + so, Al + goA);
        cp16(sbase + SB_H + so, Bh + goB);
        cp16(sbase + SB_L + so, Bl + goB);
    }
}

__global__ __launch_bounds__(256)
void gemm_mma(const __nv_bfloat16* __restrict__ Ah, const __nv_bfloat16* __restrict__ Al,
              const __nv_bfloat16* __restrict__ Bh, const __nv_bfloat16* __restrict__ Bl,
              const float* __restrict__ bias, float* __restrict__ C,
              int N, int Kpad, int act) {
    extern __shared__ char smem[];
    const uint32_t s0 = smem_u32(smem);
    const int tid = threadIdx.x, lane = tid & 31, wid = tid >> 5;
    const int wm = wid >> 2, wn = wid & 3;          // 2 x 4 warp grid
    const int nt = blockIdx.x, mt = blockIdx.y;
    const int arow0 = mt * 128, brow0 = nt * 128;
    const int nIter = Kpad / 32;

    float acc[4][4][4];
#pragma unroll
    for (int i = 0; i < 4; i++)
#pragma unroll
        for (int j = 0; j < 4; j++)
#pragma unroll
            for (int r = 0; r < 4; r++) acc[i][j][r] = 0.f;

    load_stage(s0, Ah, Al, Bh, Bl, arow0, brow0, Kpad, 0, tid);
    cp_commit();

    const int lr = lane & 15, lc = lane >> 4;                       // A ldmatrix addr
    const int br = (lane & 7) + ((lane >> 4) & 1) * 8;              // B ldmatrix addr
    const int bc = (lane >> 3) & 1;

    for (int it = 0; it < nIter; it++) {
        if (it + 1 < nIter) {
            load_stage(s0 + ((it + 1) & 1) * STG, Ah, Al, Bh, Bl,
                       arow0, brow0, Kpad, (it + 1) * 32, tid);
            cp_commit();
            cp_wait<1>();
        } else {
            cp_wait<0>();
        }
        __syncthreads();
        const uint32_t base = s0 + (it & 1) * STG;
#pragma unroll
        for (int ks = 0; ks < 2; ks++) {
            uint32_t ah[4][4], al[4][4], bh[4][2], bl[4][2];
#pragma unroll
            for (int ma = 0; ma < 4; ma++) {
                uint32_t addr = base + (uint32_t)((wm * 64 + ma * 16 + lr) * 80 + ks * 32 + lc * 16);
                ldm4(ah[ma], addr);
                ldm4(al[ma], addr + SA_L);
            }
#pragma unroll
            for (int nb = 0; nb < 2; nb++) {
                uint32_t addr = base + SB_H + (uint32_t)((wn * 32 + nb * 16 + br) * 80 + ks * 32 + bc * 16);
                uint32_t tmp[4];
                ldm4(tmp, addr);
                bh[nb * 2][0] = tmp[0]; bh[nb * 2][1] = tmp[1];
                bh[nb * 2 + 1][0] = tmp[2]; bh[nb * 2 + 1][1] = tmp[3];
                ldm4(tmp, addr + SA_L);
                bl[nb * 2][0] = tmp[0]; bl[nb * 2][1] = tmp[1];
                bl[nb * 2 + 1][0] = tmp[2]; bl[nb * 2 + 1][1] = tmp[3];
            }
#pragma unroll
            for (int ma = 0; ma < 4; ma++)
#pragma unroll
                for (int na = 0; na < 4; na++) mma_bf16(acc[ma][na], ah[ma], bh[na]);
#pragma unroll
            for (int ma = 0; ma < 4; ma++)
#pragma unroll
                for (int na = 0; na < 4; na++) mma_bf16(acc[ma][na], ah[ma], bl[na]);
#pragma unroll
            for (int ma = 0; ma < 4; ma++)
#pragma unroll
                for (int na = 0; na < 4; na++) mma_bf16(acc[ma][na], al[ma], bh[na]);
        }
        __syncthreads();
    }

    // epilogue: d0,d1 -> (row, col..col+1); d2,d3 -> (row+8, ...)
    const int rbase = mt * 128 + wm * 64 + (lane >> 2);
    const int cbase = nt * 128 + wn * 32 + (lane & 3) * 2;
#pragma unroll
    for (int ma = 0; ma < 4; ma++) {
#pragma unroll
        for (int na = 0; na < 4; na++) {
            int col = cbase + na * 8;
            if (col < N) {
                float b0 = 0.f, b1 = 0.f;
                if (bias) { b0 = bias[col]; b1 = bias[col + 1]; }
#pragma unroll
                for (int half = 0; half < 2; half++) {
                    int row = rbase + ma * 16 + half * 8;
                    float v0 = acc[ma][na][half * 2 + 0] + b0;
                    float v1 = acc[ma][na][half * 2 + 1] + b1;
                    if (act) {
                        v0 = 0.5f * v0 * (1.0f + erff(v0 * 0.70710678118654752f));
                        v1 = 0.5f * v1 * (1.0f + erff(v1 * 0.70710678118654752f));
                    }
                    *(float2*)(C + (size_t)row * N + col) = make_float2(v0, v1);
                }
            }
        }
    }
}

// ---------------- layernorm ----------------------------------------------------
__global__ void ln_kernel(const float* __restrict__ x,
                          const float* __restrict__ g,
                          const float* __restrict__ b,
                          float* __restrict__ out) {
    const int row = blockIdx.x;
    const float* xr = x + row * DMODEL;
    float s = 0.f, s2 = 0.f;
    for (int i = threadIdx.x; i < DMODEL; i += blockDim.x) {
        float v = xr[i];
        s += v; s2 += v * v;
    }
    __shared__ float red[64];
    for (int o = 16; o; o >>= 1) {
        s  += __shfl_down_sync(0xffffffffu, s,  o);
        s2 += __shfl_down_sync(0xffffffffu, s2, o);
    }
    int wid = threadIdx.x >> 5, lid = threadIdx.x & 31;
    if (lid == 0) { red[wid] = s; red[32 + wid] = s2; }
    __syncthreads();
    if (threadIdx.x == 0) {
        float a = 0.f, a2 = 0.f;
        int nw = blockDim.x >> 5;
        for (int i = 0; i < nw; i++) { a += red[i]; a2 += red[32 + i]; }
        red[0] = a; red[1] = a2;
    }
    __syncthreads();
    float mu  = red[0] * (1.0f / DMODEL);
    float var = red[1] * (1.0f / DMODEL) - mu * mu;
    float inv = rsqrtf(var + 1e-5f);
    float* o = out + row * DMODEL;
    for (int i = threadIdx.x; i < DMODEL; i += blockDim.x)
        o[i] = (xr[i] - mu) * inv * g[i] + b[i];
}

// ---------------- rank-1 pseudo-attention ---------------------------------------
__global__ __launch_bounds__(128)
void attn_kernel(const float* __restrict__ qkv, float* __restrict__ out) {
    const int bh = blockIdx.x;
    const int b = bh >> 4;
    const int h = bh & 15;
    const float* q = qkv + (size_t)b * QKVN + h * HSZ;
    const float* k = q + DMODEL;
    const float* v = q + 2 * DMODEL;

    __shared__ float ks[HSZ], vs[HSZ], qs[HSZ];
    __shared__ float kext[2];
    const int tid = threadIdx.x;
    if (tid < HSZ) { ks[tid] = k[tid]; vs[tid] = v[tid]; qs[tid] = q[tid]; }
    __syncthreads();
    if (tid < 32) {
        float mx = -1e30f, mn = 1e30f;
        for (int j = tid; j < HSZ; j += 32) {
            mx = fmaxf(mx, ks[j]);
            mn = fminf(mn, ks[j]);
        }
        for (int o = 16; o; o >>= 1) {
            mx = fmaxf(mx, __shfl_xor_sync(0xffffffffu, mx, o));
            mn = fminf(mn, __shfl_xor_sync(0xffffffffu, mn, o));
        }
        if (tid == 0) { kext[0] = mx; kext[1] = mn; }
    }
    __syncthreads();
    if (tid < HSZ) {
        const float scale = 0.025253813613805268f;  // 1568^-0.5
        float a = qs[tid] * scale;
        float m = a * ((a >= 0.f) ? kext[0] : kext[1]);
        float sum = 0.f, acc = 0.f;
#pragma unroll 7
        for (int j = 0; j < HSZ; j++) {
            float e = __expf(fmaf(a, ks[j], -m));
            sum += e;
            acc = fmaf(e, vs[j], acc);
        }
        out[(size_t)b * DMODEL + h * HSZ + tid] = acc / sum;
    }
}

// ---------------- launch ---------------------------------------------------------
extern "C" void kernel_launch(void* const* d_in, const int* in_sizes, int n_in,
                              void* d_out, int out_size) {
    const float* x   = (const float*)d_in[0];
    const float* Wq  = (const float*)d_in[1];
    const float* Wk  = (const float*)d_in[2];
    const float* Wv  = (const float*)d_in[3];
    const float* Wo  = (const float*)d_in[4];
    const float* bo  = (const float*)d_in[5];
    const float* g1  = (const float*)d_in[6];
    const float* b1  = (const float*)d_in[7];
    const float* g2  = (const float*)d_in[8];
    const float* b2  = (const float*)d_in[9];
    const float* W1  = (const float*)d_in[10];
    const float* b1f = (const float*)d_in[11];
    const float* W2  = (const float*)d_in[12];
    const float* b2f = (const float*)d_in[13];
    float* outp = (float*)d_out;

    float *p_h, *p_qkv, *p_attn, *p_proj, *p_h2, *p_ff1, *p_wqkv;
    __nv_bfloat16 *pAh, *pAl, *pqBh, *pqBl, *poBh, *poBl, *p1Bh, *p1Bl, *p2Bh, *p2Bl;
    cudaGetSymbolAddress((void**)&p_h,    g_h);
    cudaGetSymbolAddress((void**)&p_qkv,  g_qkv);
    cudaGetSymbolAddress((void**)&p_attn, g_attn);
    cudaGetSymbolAddress((void**)&p_proj, g_proj);
    cudaGetSymbolAddress((void**)&p_h2,   g_h2);
    cudaGetSymbolAddress((void**)&p_ff1,  g_ff1);
    cudaGetSymbolAddress((void**)&p_wqkv, g_wqkv);
    cudaGetSymbolAddress((void**)&pAh,  g_Ah);
    cudaGetSymbolAddress((void**)&pAl,  g_Al);
    cudaGetSymbolAddress((void**)&pqBh, g_qBh);
    cudaGetSymbolAddress((void**)&pqBl, g_qBl);
    cudaGetSymbolAddress((void**)&poBh, g_oBh);
    cudaGetSymbolAddress((void**)&poBl, g_oBl);
    cudaGetSymbolAddress((void**)&p1Bh, g_1Bh);
    cudaGetSymbolAddress((void**)&p1Bl, g_1Bl);
    cudaGetSymbolAddress((void**)&p2Bh, g_2Bh);
    cudaGetSymbolAddress((void**)&p2Bl, g_2Bl);

    const int SMEM_GEMM = 81920;
    cudaFuncSetAttribute(gemm_mma, cudaFuncAttributeMaxDynamicSharedMemorySize, SMEM_GEMM);

    // 0) weight repacks -> transposed bf16 hi/lo [Npad, Kpad]
    repack_qkv<<<512, 256>>>(Wq, Wk, Wv);
    repack_Bt<<<dim3(KP_D / 32, NP_QKV / 32), 256>>>(p_wqkv, DMODEL, QKVN, KP_D, pqBh, pqBl);
    repack_Bt<<<dim3(KP_D / 32, NP_WO  / 32), 256>>>(Wo,     DMODEL, DMODEL, KP_D, poBh, poBl);
    repack_Bt<<<dim3(KP_D / 32, NP_W1  / 32), 256>>>(W1,     DMODEL, FFDIM,  KP_D, p1Bh, p1Bl);
    repack_Bt<<<dim3(KP_F / 32, NP_W2  / 32), 256>>>(W2,     FFDIM,  OUTD,   KP_F, p2Bh, p2Bl);

    // 1) LN1
    ln_kernel<<<BATCH, 256>>>(x, g1, b1, p_h);

    // 2) qkv = h @ Wqkv
    repack_Ab<<<dim3((KP_D + 255) / 256, BATCH), 256>>>(p_h, DMODEL, KP_D, pAh, pAl);
    gemm_mma<<<dim3(NP_QKV / 128, 8), 256, SMEM_GEMM>>>(pAh, pAl, pqBh, pqBl, nullptr, p_qkv, QKVN, KP_D, 0);

    // 3) attention
    attn_kernel<<<BATCH * NHEAD, 128>>>(p_qkv, p_attn);

    // 4) proj = attn @ Wo + bo
    repack_Ab<<<dim3((KP_D + 255) / 256, BATCH), 256>>>(p_attn, DMODEL, KP_D, pAh, pAl);
    gemm_mma<<<dim3(NP_WO / 128, 8), 256, SMEM_GEMM>>>(pAh, pAl, poBh, poBl, bo, p_proj, DMODEL, KP_D, 0);

    // 5) LN2
    ln_kernel<<<BATCH, 256>>>(p_proj, g2, b2, p_h2);

    // 6) ff1 = gelu(h2 @ W1 + b1f)
    repack_Ab<<<dim3((KP_D + 255) / 256, BATCH), 256>>>(p_h2, DMODEL, KP_D, pAh, pAl);
    gemm_mma<<<dim3(NP_W1 / 128, 8), 256, SMEM_GEMM>>>(pAh, pAl, p1Bh, p1Bl, b1f, p_ff1, FFDIM, KP_D, 1);

    // 7) out = ff1 @ W2 + b2f
    repack_Ab<<<dim3((KP_F + 255) / 256, BATCH), 256>>>(p_ff1, FFDIM, KP_F, pAh, pAl);
    gemm_mma<<<dim3(NP_W2 / 128, 8), 256, SMEM_GEMM>>>(pAh, pAl, p2Bh, p2Bl, b2f, outp, OUTD, KP_F, 0);
}